// round 9
// baseline (speedup 1.0000x reference)
#include <cuda_runtime.h>
#include <math.h>
#include <stdint.h>

#define Tt   2048
#define Hh   2048
#define NHh  16
#define HDd  128
#define Ee   16
#define Ff   1024
#define SF   4096      // shared FFN hidden
#define CAP  8192      // padded assignment rows capacity (>= 4096 + 16*127)

// ---------------- scratch (device globals; no allocations) ----------------
__device__ float g_h   [Tt * Hh];
__device__ float g_qkv [Tt * 3 * Hh];
__device__ float g_ctx [Tt * Hh];
__device__ float g_x1  [Tt * Hh];
__device__ float g_h2  [Tt * Hh];
__device__ float g_lg  [Tt * Ee];
__device__ float g_topw[Tt * 2];
__device__ int   g_topi[Tt * 2];
__device__ int   g_cnt [Ee];
__device__ int   g_poff[Ee];
__device__ int   g_pcnt[Ee];
__device__ int   g_fill[Ee];
__device__ int   g_pos [Tt * 2];
__device__ float g_X   [(size_t)CAP * Hh];        // gathered h2 rows
__device__ float g_gu  [(size_t)CAP * 2 * Ff];    // up-proj out
__device__ float g_act [(size_t)CAP * Ff];
__device__ float g_D   [(size_t)CAP * Hh];        // down-proj out
__device__ float g_sg  [(size_t)Tt * 2 * SF];
__device__ float g_sact[(size_t)Tt * SF];
__device__ float g_sh  [Tt * Hh];

// ---------------- tf32 helpers ----------------
__device__ __forceinline__ unsigned f2tf32(float x)
{
    unsigned y;
    asm("cvt.rna.tf32.f32 %0, %1;" : "=r"(y) : "f"(x));
    return y;
}

__device__ __forceinline__ void st_tf32x4(float* p, float4 v)
{
    uint4 u;
    u.x = f2tf32(v.x); u.y = f2tf32(v.y); u.z = f2tf32(v.z); u.w = f2tf32(v.w);
    *(uint4*)p = u;
}

__device__ __forceinline__ void mma_tf32(float* c, const unsigned* a,
                                         unsigned b0, unsigned b1)
{
    asm volatile(
        "mma.sync.aligned.m16n8k8.row.col.f32.tf32.tf32.f32 "
        "{%0,%1,%2,%3}, {%4,%5,%6,%7}, {%8,%9}, {%0,%1,%2,%3};"
        : "+f"(c[0]), "+f"(c[1]), "+f"(c[2]), "+f"(c[3])
        : "r"(a[0]), "r"(a[1]), "r"(a[2]), "r"(a[3]), "r"(b0), "r"(b1));
}

// ---------------- rmsnorm ----------------
__global__ void rmsnorm_k(const float* __restrict__ x, const float* __restrict__ g,
                          float* __restrict__ out)
{
    int t = blockIdx.x;
    const float* xr = x + (size_t)t * Hh;
    float* orow = out + (size_t)t * Hh;
    __shared__ float red[256];
    float ss = 0.f;
    for (int i = threadIdx.x; i < Hh; i += 256) { float v = xr[i]; ss += v * v; }
    red[threadIdx.x] = ss;
    __syncthreads();
    for (int s = 128; s > 0; s >>= 1) {
        if (threadIdx.x < s) red[threadIdx.x] += red[threadIdx.x + s];
        __syncthreads();
    }
    float scale = rsqrtf(red[0] / (float)Hh + 1e-6f);
    for (int i = threadIdx.x; i < Hh; i += 256) orow[i] = xr[i] * scale * g[i];
}

// ---------------- tf32 tensor-core GEMM: C = A*B (+Cadd), batched/grouped ----------------
// Block tile 128x128, BK=32, 8 warps each 64x32, mma m16n8k8 tf32. 2 CTAs/SM.
#define GBM 128
#define GBN 128
#define GBK 32

__global__ __launch_bounds__(256, 2)
void gemm_tc(const float* __restrict__ A, int lda,
             const float* __restrict__ B, int ldb,
             float* __restrict__ C, int ldc,
             int M, int N, int K,
             const float* __restrict__ Cadd,
             long sAz, long sBz, long sCz,
             const int* __restrict__ grp_off, const int* __restrict__ grp_cnt)
{
    int z = blockIdx.z;
    if (grp_off) {
        int off = grp_off[z];
        int cnt = grp_cnt[z];
        if ((int)blockIdx.y * GBM >= cnt) return;
        A += (long)off * lda;
        C += (long)off * ldc;
        M = cnt;
        B += (long)z * sBz;
    } else {
        A += (long)z * sAz; B += (long)z * sBz; C += (long)z * sCz;
        if (Cadd) Cadd += (long)z * sCz;
        if ((int)blockIdx.y * GBM >= M) return;
    }

    __shared__ float As[GBM][36];   // padded: frag loads conflict-free
    __shared__ float Bs[GBK][136];  // padded: frag loads conflict-free

    int tid  = threadIdx.x;
    int warp = tid >> 5, lane = tid & 31;
    int grp  = lane >> 2, tid4 = lane & 3;
    int wr   = (warp >> 2) * 64;   // warp row base within tile
    int wc   = (warp & 3) * 32;    // warp col base within tile
    int row0 = blockIdx.y * GBM;
    int col0 = blockIdx.x * GBN;

    float c[4][4][4];
    #pragma unroll
    for (int mi = 0; mi < 4; mi++)
        #pragma unroll
        for (int nj = 0; nj < 4; nj++)
            #pragma unroll
            for (int r = 0; r < 4; r++) c[mi][nj][r] = 0.f;

    float4 ra[4], rb[4];
    const float4 z4 = make_float4(0.f, 0.f, 0.f, 0.f);

    // preload chunk 0
    #pragma unroll
    for (int j = 0; j < 4; j++) {
        int id = tid + j * 256;
        int r  = id >> 3, cb = (id & 7) * 4;
        ra[j] = (row0 + r < M) ? *(const float4*)(A + (long)(row0 + r) * lda + cb) : z4;
        int kr = id >> 5, cc = (id & 31) * 4;
        rb[j] = (col0 + cc < N) ? *(const float4*)(B + (long)kr * ldb + col0 + cc) : z4;
    }

    int nchunks = K / GBK;
    for (int ch = 0; ch < nchunks; ch++) {
        __syncthreads();
        #pragma unroll
        for (int j = 0; j < 4; j++) {
            int id = tid + j * 256;
            int r  = id >> 3, cb = (id & 7) * 4;
            st_tf32x4(&As[r][cb], ra[j]);
            int kr = id >> 5, cc = (id & 31) * 4;
            st_tf32x4(&Bs[kr][cc], rb[j]);
        }
        __syncthreads();
        if (ch + 1 < nchunks) {
            int k0 = (ch + 1) * GBK;
            #pragma unroll
            for (int j = 0; j < 4; j++) {
                int id = tid + j * 256;
                int r  = id >> 3, cb = (id & 7) * 4;
                ra[j] = (row0 + r < M) ? *(const float4*)(A + (long)(row0 + r) * lda + k0 + cb) : z4;
                int kr = id >> 5, cc = (id & 31) * 4;
                rb[j] = (col0 + cc < N) ? *(const float4*)(B + (long)(k0 + kr) * ldb + col0 + cc) : z4;
            }
        }
        #pragma unroll
        for (int ks = 0; ks < 4; ks++) {
            unsigned af[4][4];
            #pragma unroll
            for (int mi = 0; mi < 4; mi++) {
                int m = wr + mi * 16;
                af[mi][0] = __float_as_uint(As[m + grp][ks * 8 + tid4]);
                af[mi][1] = __float_as_uint(As[m + grp + 8][ks * 8 + tid4]);
                af[mi][2] = __float_as_uint(As[m + grp][ks * 8 + tid4 + 4]);
                af[mi][3] = __float_as_uint(As[m + grp + 8][ks * 8 + tid4 + 4]);
            }
            #pragma unroll
            for (int nj = 0; nj < 4; nj++) {
                unsigned b0 = __float_as_uint(Bs[ks * 8 + tid4][wc + nj * 8 + grp]);
                unsigned b1 = __float_as_uint(Bs[ks * 8 + tid4 + 4][wc + nj * 8 + grp]);
                #pragma unroll
                for (int mi = 0; mi < 4; mi++)
                    mma_tf32(c[mi][nj], af[mi], b0, b1);
            }
        }
    }

    // epilogue
    #pragma unroll
    for (int mi = 0; mi < 4; mi++) {
        int r0 = row0 + wr + mi * 16 + grp;
        #pragma unroll
        for (int nj = 0; nj < 4; nj++) {
            int cb = col0 + wc + nj * 8 + tid4 * 2;
            #pragma unroll
            for (int half = 0; half < 2; half++) {
                int rr = r0 + half * 8;
                if (rr >= M) continue;
                float v0 = c[mi][nj][half * 2];
                float v1 = c[mi][nj][half * 2 + 1];
                if (Cadd) {
                    v0 += Cadd[(long)rr * ldc + cb];
                    v1 += Cadd[(long)rr * ldc + cb + 1];
                }
                if (cb < N)     C[(long)rr * ldc + cb]     = v0;
                if (cb + 1 < N) C[(long)rr * ldc + cb + 1] = v1;
            }
        }
    }
}

// ---------------- RoPE (in place on q,k parts of qkv) ----------------
__global__ void rope_k(float* __restrict__ qkv)
{
    int idx = blockIdx.x * 256 + threadIdx.x;
    // layout of idx: t (11b) | part (1b) | head (4b) | d (6b)
    if (idx >= Tt * 2 * NHh * 64) return;
    int d  = idx & 63;
    int hh = (idx >> 6) & 15;
    int p  = (idx >> 10) & 1;
    int t  = idx >> 11;
    float inv = 1.0f / powf(10000.0f, (float)d * (1.0f / 64.0f));
    float ang = (float)t * inv;
    float c = cosf(ang), s = sinf(ang);
    size_t base = (size_t)t * (3 * Hh) + (size_t)p * Hh + hh * HDd;
    float x1v = qkv[base + d];
    float x2v = qkv[base + d + 64];
    qkv[base + d]      = x1v * c - x2v * s;
    qkv[base + d + 64] = x1v * s + x2v * c;
}

// ---------------- fused flash attention (tf32 mma, online softmax) ----------------
// 128 queries x 64 keys per tile; 8 warps, each owns 16 query rows.
// Qs/Ks/Vs stride 132 (frag loads conflict-free), Ps stride 68.
#define FSTR 132
#define PSTR 68
#define FQ   128    // queries per CTA

__global__ __launch_bounds__(256, 1)
void flash_k(const float* __restrict__ qkv, float* __restrict__ ctx)
{
    extern __shared__ float sm[];
    float* Qs = sm;                          // [128][132]
    float* Ks = sm + FQ * FSTR;              // [64][132]
    float* Vs = sm + (FQ + 64) * FSTR;       // [64][132]
    float* Ps = sm + (FQ + 128) * FSTR;      // [128][68]

    int h  = blockIdx.y;
    int qt = gridDim.x - 1 - blockIdx.x;     // longest blocks launch first
    int t0 = qt * FQ;
    int tid = threadIdx.x, warp = tid >> 5, lane = tid & 31;
    int grp = lane >> 2, tid4 = lane & 3;

    // load + convert Q tile (128 x 128)
    for (int i = tid; i < FQ * 32; i += 256) {
        int r = i >> 5, c4 = (i & 31) * 4;
        float4 v = *(const float4*)(qkv + (size_t)(t0 + r) * (3 * Hh) + h * HDd + c4);
        st_tf32x4(&Qs[r * FSTR + c4], v);
    }

    float o[16][4];
    #pragma unroll
    for (int a = 0; a < 16; a++)
        #pragma unroll
        for (int b = 0; b < 4; b++) o[a][b] = 0.f;
    float m0 = -1e30f, m1 = -1e30f, l0 = 0.f, l1 = 0.f;
    int prow = warp * 16 + grp;
    int r0 = t0 + prow;
    int r1 = r0 + 8;
    int wrow_max = t0 + warp * 16 + 15;      // highest query row in this warp

    int ntiles = (t0 + FQ) / 64;
    for (int j = 0; j < ntiles; j++) {
        int s0 = j * 64;
        __syncthreads();
        for (int i = tid; i < 64 * 32; i += 256) {
            int r = i >> 5, c4 = (i & 31) * 4;
            const float* base = qkv + (size_t)(s0 + r) * (3 * Hh) + h * HDd + c4;
            st_tf32x4(&Ks[r * FSTR + c4], *(const float4*)(base + Hh));
            st_tf32x4(&Vs[r * FSTR + c4], *(const float4*)(base + 2 * Hh));
        }
        __syncthreads();

        if (s0 > wrow_max) continue;          // warp-uniform: tile fully masked for this warp

        // ---- scores tile: S = Q Kt ----
        float s[8][4];
        #pragma unroll
        for (int nj = 0; nj < 8; nj++)
            #pragma unroll
            for (int r = 0; r < 4; r++) s[nj][r] = 0.f;
        #pragma unroll
        for (int ks = 0; ks < 16; ks++) {
            unsigned af[4];
            af[0] = __float_as_uint(Qs[prow * FSTR + ks * 8 + tid4]);
            af[1] = __float_as_uint(Qs[(prow + 8) * FSTR + ks * 8 + tid4]);
            af[2] = __float_as_uint(Qs[prow * FSTR + ks * 8 + tid4 + 4]);
            af[3] = __float_as_uint(Qs[(prow + 8) * FSTR + ks * 8 + tid4 + 4]);
            #pragma unroll
            for (int nj = 0; nj < 8; nj++) {
                unsigned b0 = __float_as_uint(Ks[(nj * 8 + grp) * FSTR + ks * 8 + tid4]);
                unsigned b1 = __float_as_uint(Ks[(nj * 8 + grp) * FSTR + ks * 8 + tid4 + 4]);
                mma_tf32(s[nj], af, b0, b1);
            }
        }

        // ---- online softmax ----
        const float scale = 0.08838834764831845f; // 1/sqrt(128)
        bool diag = (s0 + 63 >= t0);               // only last two tiles touch diagonal
        float tm0 = -1e30f, tm1 = -1e30f;
        #pragma unroll
        for (int nj = 0; nj < 8; nj++) {
            #pragma unroll
            for (int r = 0; r < 4; r++) s[nj][r] *= scale;
            if (diag) {
                int c0 = s0 + nj * 8 + tid4 * 2;
                if (c0     > r0) s[nj][0] = -1e30f;
                if (c0 + 1 > r0) s[nj][1] = -1e30f;
                if (c0     > r1) s[nj][2] = -1e30f;
                if (c0 + 1 > r1) s[nj][3] = -1e30f;
            }
            tm0 = fmaxf(tm0, fmaxf(s[nj][0], s[nj][1]));
            tm1 = fmaxf(tm1, fmaxf(s[nj][2], s[nj][3]));
        }
        #pragma unroll
        for (int off = 1; off < 4; off <<= 1) {
            tm0 = fmaxf(tm0, __shfl_xor_sync(0xffffffff, tm0, off));
            tm1 = fmaxf(tm1, __shfl_xor_sync(0xffffffff, tm1, off));
        }
        float nm0 = fmaxf(m0, tm0), nm1 = fmaxf(m1, tm1);
        float f0 = __expf(m0 - nm0), f1 = __expf(m1 - nm1);
        float rs0 = 0.f, rs1 = 0.f;
        #pragma unroll
        for (int nj = 0; nj < 8; nj++) {
            float p0 = __expf(s[nj][0] - nm0);
            float p1 = __expf(s[nj][1] - nm0);
            float p2 = __expf(s[nj][2] - nm1);
            float p3 = __expf(s[nj][3] - nm1);
            rs0 += p0 + p1; rs1 += p2 + p3;
            int pc = nj * 8 + tid4 * 2;
            Ps[prow * PSTR + pc]           = __uint_as_float(f2tf32(p0));
            Ps[prow * PSTR + pc + 1]       = __uint_as_float(f2tf32(p1));
            Ps[(prow + 8) * PSTR + pc]     = __uint_as_float(f2tf32(p2));
            Ps[(prow + 8) * PSTR + pc + 1] = __uint_as_float(f2tf32(p3));
        }
        l0 = l0 * f0 + rs0;
        l1 = l1 * f1 + rs1;
        #pragma unroll
        for (int nj = 0; nj < 16; nj++) {
            o[nj][0] *= f0; o[nj][1] *= f0;
            o[nj][2] *= f1; o[nj][3] *= f1;
        }
        __syncwarp();   // Ps rows are warp-private: warp-level ordering suffices

        // ---- O += P V ----
        #pragma unroll
        for (int ks = 0; ks < 8; ks++) {
            unsigned af[4];
            af[0] = __float_as_uint(Ps[prow * PSTR + ks * 8 + tid4]);
            af[1] = __float_as_uint(Ps[(prow + 8) * PSTR + ks * 8 + tid4]);
            af[2] = __float_as_uint(Ps[prow * PSTR + ks * 8 + tid4 + 4]);
            af[3] = __float_as_uint(Ps[(prow + 8) * PSTR + ks * 8 + tid4 + 4]);
            #pragma unroll
            for (int nj = 0; nj < 16; nj++) {
                unsigned b0 = __float_as_uint(Vs[(ks * 8 + tid4) * FSTR + nj * 8 + grp]);
                unsigned b1 = __float_as_uint(Vs[(ks * 8 + tid4 + 4) * FSTR + nj * 8 + grp]);
                mma_tf32(o[nj], af, b0, b1);
            }
        }
        m0 = nm0; m1 = nm1;
    }

    // reduce l across the quad (each thread held a column subset)
    #pragma unroll
    for (int off = 1; off < 4; off <<= 1) {
        l0 += __shfl_xor_sync(0xffffffff, l0, off);
        l1 += __shfl_xor_sync(0xffffffff, l1, off);
    }
    float inv0 = 1.f / l0, inv1 = 1.f / l1;
    #pragma unroll
    for (int nj = 0; nj < 16; nj++) {
        int cc = h * HDd + nj * 8 + tid4 * 2;
        ctx[(size_t)r0 * Hh + cc]     = o[nj][0] * inv0;
        ctx[(size_t)r0 * Hh + cc + 1] = o[nj][1] * inv0;
        ctx[(size_t)r1 * Hh + cc]     = o[nj][2] * inv1;
        ctx[(size_t)r1 * Hh + cc + 1] = o[nj][3] * inv1;
    }
}

// ---------------- router top-2 ----------------
__global__ void topk_k(const float* __restrict__ lg, float* __restrict__ topw,
                       int* __restrict__ topi, int* __restrict__ cnt)
{
    int t = blockIdx.x * blockDim.x + threadIdx.x;
    if (t >= Tt) return;
    const float* l = lg + (size_t)t * Ee;
    float b0 = -1e30f; int i0 = 0;
    #pragma unroll
    for (int e = 0; e < Ee; e++) { float v = l[e]; if (v > b0) { b0 = v; i0 = e; } }
    float b1 = -1e30f; int i1 = 0;
    #pragma unroll
    for (int e = 0; e < Ee; e++) { if (e == i0) continue; float v = l[e]; if (v > b1) { b1 = v; i1 = e; } }
    float e1 = expf(b1 - b0);
    float s = 1.0f + e1;
    topw[t * 2]     = 1.0f / s;
    topw[t * 2 + 1] = e1 / s;
    topi[t * 2]     = i0;
    topi[t * 2 + 1] = i1;
    atomicAdd(&cnt[i0], 1);
    atomicAdd(&cnt[i1], 1);
}

// ---------------- scan: padded offsets (pad to 128 = GBM) ----------------
__global__ void scan_k(const int* __restrict__ cnt, int* __restrict__ poff,
                       int* __restrict__ pcnt, int* __restrict__ fill)
{
    if (threadIdx.x == 0 && blockIdx.x == 0) {
        int run = 0;
        for (int e = 0; e < Ee; e++) {
            poff[e] = run;
            int pc = (cnt[e] + 127) & ~127;
            pcnt[e] = pc;
            run += pc;
            fill[e] = 0;
        }
    }
}

// ---------------- scatter: gather h2 rows into expert-sorted X ----------------
__global__ void scatter_k(const float* __restrict__ h2, const int* __restrict__ topi,
                          const int* __restrict__ poff, int* __restrict__ fill,
                          int* __restrict__ pos, float* __restrict__ X)
{
    int a = blockIdx.x;   // assignment id 0..2T-1
    __shared__ int sp;
    if (threadIdx.x == 0) {
        int e = topi[a];
        sp = poff[e] + atomicAdd(&fill[e], 1);
        pos[a] = sp;
    }
    __syncthreads();
    int p = sp;
    int t = a >> 1;
    const float* src = h2 + (size_t)t * Hh;
    float* dst = X + (size_t)p * Hh;
    for (int i = threadIdx.x; i < Hh; i += 256) dst[i] = src[i];
}

// ---------------- silu(g)*u ----------------
__global__ void silu_mul_k(const float* __restrict__ in, float* __restrict__ out,
                           long total, int Fh, int ldin)
{
    long idx = (long)blockIdx.x * 256 + threadIdx.x;
    if (idx >= total) return;
    long r = idx / Fh;
    int  f = (int)(idx - r * Fh);
    float gv = in[r * ldin + f];
    float uv = in[r * ldin + Fh + f];
    float sv = gv / (1.0f + expf(-gv));
    out[idx] = sv * uv;
}

// ---------------- final combine ----------------
__global__ void final_k(const float* __restrict__ x1, const float* __restrict__ sh,
                        const float* __restrict__ D, const float* __restrict__ topw,
                        const int* __restrict__ pos, float* __restrict__ out)
{
    int idx = blockIdx.x * 256 + threadIdx.x;
    int t = idx >> 11;       // /2048
    int c = idx & 2047;
    if (t >= Tt) return;
    int a = t * 2;
    float v = x1[idx] + sh[idx];
    v += topw[a]     * D[(size_t)pos[a]     * Hh + c];
    v += topw[a + 1] * D[(size_t)pos[a + 1] * Hh + c];
    out[idx] = v;
}

// ---------------- host side ----------------
template <typename Tp>
static Tp* symaddr(const void* sym)
{
    void* p = nullptr;
    cudaGetSymbolAddress(&p, sym);
    return (Tp*)p;
}

static void launch_gemm(const float* A, int lda, const float* B, int ldb,
                        float* C, int ldc, int M, int N, int K,
                        const float* Cadd, long sAz, long sBz, long sCz, int Z,
                        const int* goff, const int* gcnt)
{
    dim3 grid((N + GBN - 1) / GBN, (M + GBM - 1) / GBM, Z);
    gemm_tc<<<grid, 256>>>(A, lda, B, ldb, C, ldc, M, N, K, Cadd,
                           sAz, sBz, sCz, goff, gcnt);
}

extern "C" void kernel_launch(void* const* d_in, const int* in_sizes, int n_in,
                              void* d_out, int out_size)
{
    const float* x        = (const float*)d_in[0];
    const float* gamma1   = (const float*)d_in[1];
    const float* gamma2   = (const float*)d_in[2];
    const float* w_qkv    = (const float*)d_in[3];
    const float* w_o      = (const float*)d_in[4];
    const float* gate_w   = (const float*)d_in[5];
    const float* moe_up   = (const float*)d_in[6];
    const float* moe_down = (const float*)d_in[7];
    const float* sw13     = (const float*)d_in[8];
    const float* sdown    = (const float*)d_in[9];
    float* out = (float*)d_out;

    float* h    = symaddr<float>(&g_h);
    float* qkv  = symaddr<float>(&g_qkv);
    float* ctx  = symaddr<float>(&g_ctx);
    float* x1   = symaddr<float>(&g_x1);
    float* h2   = symaddr<float>(&g_h2);
    float* lg   = symaddr<float>(&g_lg);
    float* topw = symaddr<float>(&g_topw);
    int*   topi = symaddr<int>(&g_topi);
    int*   cnt  = symaddr<int>(&g_cnt);
    int*   poff = symaddr<int>(&g_poff);
    int*   pcnt = symaddr<int>(&g_pcnt);
    int*   fill = symaddr<int>(&g_fill);
    int*   pos  = symaddr<int>(&g_pos);
    float* X    = symaddr<float>(&g_X);
    float* gu   = symaddr<float>(&g_gu);
    float* act  = symaddr<float>(&g_act);
    float* D    = symaddr<float>(&g_D);
    float* sg   = symaddr<float>(&g_sg);
    float* sact = symaddr<float>(&g_sact);
    float* sh   = symaddr<float>(&g_sh);

    // 1. h = rmsnorm(x, gamma1)
    rmsnorm_k<<<Tt, 256>>>(x, gamma1, h);
    // 2. qkv = h @ w_qkv
    launch_gemm(h, Hh, w_qkv, 3 * Hh, qkv, 3 * Hh, Tt, 3 * Hh, Hh,
                nullptr, 0, 0, 0, 1, nullptr, nullptr);
    // 3. rope(q, k)
    rope_k<<<(Tt * 2 * NHh * 64 + 255) / 256, 256>>>(qkv);
    // 4-6. fused flash attention -> ctx
    {
        int smem = ((FQ + 128) * FSTR + FQ * PSTR) * (int)sizeof(float);
        cudaFuncSetAttribute(flash_k, cudaFuncAttributeMaxDynamicSharedMemorySize, smem);
        dim3 grid(Tt / FQ, NHh);
        flash_k<<<grid, 256, smem>>>(qkv, ctx);
    }
    // 7. x1 = x + ctx @ w_o
    launch_gemm(ctx, Hh, w_o, Hh, x1, Hh, Tt, Hh, Hh,
                x, 0, 0, 0, 1, nullptr, nullptr);
    // 8. h2 = rmsnorm(x1, gamma2)
    rmsnorm_k<<<Tt, 256>>>(x1, gamma2, h2);
    // 9. router logits
    launch_gemm(h2, Hh, gate_w, Ee, lg, Ee, Tt, Ee, Hh,
                nullptr, 0, 0, 0, 1, nullptr, nullptr);
    // 10. top-2 (+ counts)
    cudaMemsetAsync(cnt, 0, Ee * sizeof(int));
    topk_k<<<(Tt + 255) / 256, 256>>>(lg, topw, topi, cnt);
    // 11. scan -> padded offsets
    scan_k<<<1, 32>>>(cnt, poff, pcnt, fill);
    // 12. gather rows by expert
    scatter_k<<<Tt * 2, 256>>>(h2, topi, poff, fill, pos, X);
    // 13. grouped up-proj: gu = X @ moe_up[e]
    launch_gemm(X, Hh, moe_up, 2 * Ff, gu, 2 * Ff, Tt, 2 * Ff, Hh,
                nullptr, 0, (long)Hh * 2 * Ff, 0, Ee, poff, pcnt);
    // 14. act = silu(g)*u over all CAP rows (padded rows unread later)
    {
        long total = (long)CAP * Ff;
        silu_mul_k<<<(int)((total + 255) / 256), 256>>>(gu, act, total, Ff, 2 * Ff);
    }
    // 15. grouped down-proj: D = act @ moe_down[e]
    launch_gemm(act, Ff, moe_down, Hh, D, Hh, Tt, Hh, Ff,
                nullptr, 0, (long)Ff * Hh, 0, Ee, poff, pcnt);
    // 16. shared FFN
    launch_gemm(h2, Hh, sw13, 2 * SF, sg, 2 * SF, Tt, 2 * SF, Hh,
                nullptr, 0, 0, 0, 1, nullptr, nullptr);
    {
        long total = (long)Tt * SF;
        silu_mul_k<<<(int)((total + 255) / 256), 256>>>(sg, sact, total, SF, 2 * SF);
    }
    launch_gemm(sact, SF, sdown, Hh, sh, Hh, Tt, Hh, SF,
                nullptr, 0, 0, 0, 1, nullptr, nullptr);
    // 17. out = x1 + moe + shared
    final_k<<<(Tt * Hh) / 256, 256>>>(x1, sh, D, topw, pos, out);
}

// round 11
// speedup vs baseline: 1.1066x; 1.1066x over previous
#include <cuda_runtime.h>
#include <math.h>
#include <stdint.h>

#define Tt   2048
#define Hh   2048
#define NHh  16
#define HDd  128
#define Ee   16
#define Ff   1024
#define SF   4096      // shared FFN hidden
#define CAP  8192      // padded assignment rows capacity (>= 4096 + 16*127)

// ---------------- scratch (device globals; no allocations) ----------------
__device__ float g_h   [Tt * Hh];
__device__ float g_qkv [Tt * 3 * Hh];
__device__ float g_ctx [Tt * Hh];
__device__ float g_x1  [Tt * Hh];
__device__ float g_h2  [Tt * Hh];
__device__ float g_lg  [Tt * Ee];
__device__ float g_topw[Tt * 2];
__device__ int   g_topi[Tt * 2];
__device__ int   g_cnt [Ee];
__device__ int   g_poff[Ee];
__device__ int   g_pcnt[Ee];
__device__ int   g_fill[Ee];
__device__ int   g_pos [Tt * 2];
__device__ float g_X   [(size_t)CAP * Hh];        // gathered h2 rows
__device__ float g_gu  [(size_t)CAP * 2 * Ff];    // up-proj out
__device__ float g_act [(size_t)CAP * Ff];
__device__ float g_D   [(size_t)CAP * Hh];        // down-proj out
__device__ float g_sg  [(size_t)Tt * 2 * SF];
__device__ float g_sact[(size_t)Tt * SF];
__device__ float g_sh  [Tt * Hh];

// ---------------- tf32 helpers ----------------
__device__ __forceinline__ unsigned f2tf32(float x)
{
    unsigned y;
    asm("cvt.rna.tf32.f32 %0, %1;" : "=r"(y) : "f"(x));
    return y;
}

__device__ __forceinline__ void st_tf32x4(float* p, float4 v)
{
    uint4 u;
    u.x = f2tf32(v.x); u.y = f2tf32(v.y); u.z = f2tf32(v.z); u.w = f2tf32(v.w);
    *(uint4*)p = u;
}

__device__ __forceinline__ void mma_tf32(float* c, const unsigned* a,
                                         unsigned b0, unsigned b1)
{
    asm volatile(
        "mma.sync.aligned.m16n8k8.row.col.f32.tf32.tf32.f32 "
        "{%0,%1,%2,%3}, {%4,%5,%6,%7}, {%8,%9}, {%0,%1,%2,%3};"
        : "+f"(c[0]), "+f"(c[1]), "+f"(c[2]), "+f"(c[3])
        : "r"(a[0]), "r"(a[1]), "r"(a[2]), "r"(a[3]), "r"(b0), "r"(b1));
}

// ---------------- rmsnorm ----------------
__global__ void rmsnorm_k(const float* __restrict__ x, const float* __restrict__ g,
                          float* __restrict__ out)
{
    int t = blockIdx.x;
    const float* xr = x + (size_t)t * Hh;
    float* orow = out + (size_t)t * Hh;
    __shared__ float red[256];
    float ss = 0.f;
    for (int i = threadIdx.x; i < Hh; i += 256) { float v = xr[i]; ss += v * v; }
    red[threadIdx.x] = ss;
    __syncthreads();
    for (int s = 128; s > 0; s >>= 1) {
        if (threadIdx.x < s) red[threadIdx.x] += red[threadIdx.x + s];
        __syncthreads();
    }
    float scale = rsqrtf(red[0] / (float)Hh + 1e-6f);
    for (int i = threadIdx.x; i < Hh; i += 256) orow[i] = xr[i] * scale * g[i];
}

// ---------------- tf32 tensor-core GEMM: C = A*B (+Cadd), batched/grouped ----------------
// Block tile 128x128, BK=32, 8 warps each 64x32, mma m16n8k8 tf32.
// Double-buffered SMEM (ping-pong), ONE __syncthreads per chunk.
#define GBM 128
#define GBN 128
#define GBK 32
#define ABUF (GBM * 36)            // 4608 floats
#define BBUF (GBK * 136)           // 4352 floats
#define GBUF (ABUF + BBUF)         // 8960 floats per buffer
#define GSMEM_BYTES (2 * GBUF * 4) // 71680 bytes

__global__ __launch_bounds__(256)
void gemm_tc(const float* __restrict__ A, int lda,
             const float* __restrict__ B, int ldb,
             float* __restrict__ C, int ldc,
             int M, int N, int K,
             const float* __restrict__ Cadd,
             long sAz, long sBz, long sCz,
             const int* __restrict__ grp_off, const int* __restrict__ grp_cnt)
{
    int z = blockIdx.z;
    if (grp_off) {
        int off = grp_off[z];
        int cnt = grp_cnt[z];
        if ((int)blockIdx.y * GBM >= cnt) return;
        A += (long)off * lda;
        C += (long)off * ldc;
        M = cnt;
        B += (long)z * sBz;
    } else {
        A += (long)z * sAz; B += (long)z * sBz; C += (long)z * sCz;
        if (Cadd) Cadd += (long)z * sCz;
        if ((int)blockIdx.y * GBM >= M) return;
    }

    extern __shared__ float gsm[];   // [2][GBUF]: As[128][36] then Bs[32][136]

    int tid  = threadIdx.x;
    int warp = tid >> 5, lane = tid & 31;
    int grp  = lane >> 2, tid4 = lane & 3;
    int wr   = (warp >> 2) * 64;   // warp row base within tile
    int wc   = (warp & 3) * 32;    // warp col base within tile
    int row0 = blockIdx.y * GBM;
    int col0 = blockIdx.x * GBN;

    float c[4][4][4];
    #pragma unroll
    for (int mi = 0; mi < 4; mi++)
        #pragma unroll
        for (int nj = 0; nj < 4; nj++)
            #pragma unroll
            for (int r = 0; r < 4; r++) c[mi][nj][r] = 0.f;

    float4 ra[4], rb[4];
    const float4 z4 = make_float4(0.f, 0.f, 0.f, 0.f);

    // preload chunk 0
    #pragma unroll
    for (int j = 0; j < 4; j++) {
        int id = tid + j * 256;
        int r  = id >> 3, cb = (id & 7) * 4;
        ra[j] = (row0 + r < M) ? *(const float4*)(A + (long)(row0 + r) * lda + cb) : z4;
        int kr = id >> 5, cc = (id & 31) * 4;
        rb[j] = (col0 + cc < N) ? *(const float4*)(B + (long)kr * ldb + col0 + cc) : z4;
    }

    int nchunks = K / GBK;
    int p = 0;
    for (int ch = 0; ch < nchunks; ch++) {
        float* Asb = gsm + p * GBUF;
        float* Bsb = Asb + ABUF;
        // store current chunk's registers into buffer p
        #pragma unroll
        for (int j = 0; j < 4; j++) {
            int id = tid + j * 256;
            int r  = id >> 3, cb = (id & 7) * 4;
            st_tf32x4(&Asb[r * 36 + cb], ra[j]);
            int kr = id >> 5, cc = (id & 31) * 4;
            st_tf32x4(&Bsb[kr * 136 + cc], rb[j]);
        }
        __syncthreads();
        // prefetch next chunk while computing on buffer p
        if (ch + 1 < nchunks) {
            int k0 = (ch + 1) * GBK;
            #pragma unroll
            for (int j = 0; j < 4; j++) {
                int id = tid + j * 256;
                int r  = id >> 3, cb = (id & 7) * 4;
                ra[j] = (row0 + r < M) ? *(const float4*)(A + (long)(row0 + r) * lda + k0 + cb) : z4;
                int kr = id >> 5, cc = (id & 31) * 4;
                rb[j] = (col0 + cc < N) ? *(const float4*)(B + (long)(k0 + kr) * ldb + col0 + cc) : z4;
            }
        }
        #pragma unroll
        for (int ks = 0; ks < 4; ks++) {
            unsigned af[4][4];
            #pragma unroll
            for (int mi = 0; mi < 4; mi++) {
                int m = wr + mi * 16;
                af[mi][0] = __float_as_uint(Asb[(m + grp) * 36 + ks * 8 + tid4]);
                af[mi][1] = __float_as_uint(Asb[(m + grp + 8) * 36 + ks * 8 + tid4]);
                af[mi][2] = __float_as_uint(Asb[(m + grp) * 36 + ks * 8 + tid4 + 4]);
                af[mi][3] = __float_as_uint(Asb[(m + grp + 8) * 36 + ks * 8 + tid4 + 4]);
            }
            #pragma unroll
            for (int nj = 0; nj < 4; nj++) {
                unsigned b0 = __float_as_uint(Bsb[(ks * 8 + tid4) * 136 + wc + nj * 8 + grp]);
                unsigned b1 = __float_as_uint(Bsb[(ks * 8 + tid4 + 4) * 136 + wc + nj * 8 + grp]);
                #pragma unroll
                for (int mi = 0; mi < 4; mi++)
                    mma_tf32(c[mi][nj], af[mi], b0, b1);
            }
        }
        p ^= 1;
    }

    // epilogue
    #pragma unroll
    for (int mi = 0; mi < 4; mi++) {
        int r0 = row0 + wr + mi * 16 + grp;
        #pragma unroll
        for (int nj = 0; nj < 4; nj++) {
            int cb = col0 + wc + nj * 8 + tid4 * 2;
            #pragma unroll
            for (int half = 0; half < 2; half++) {
                int rr = r0 + half * 8;
                if (rr >= M) continue;
                float v0 = c[mi][nj][half * 2];
                float v1 = c[mi][nj][half * 2 + 1];
                if (Cadd) {
                    v0 += Cadd[(long)rr * ldc + cb];
                    v1 += Cadd[(long)rr * ldc + cb + 1];
                }
                if (cb < N)     C[(long)rr * ldc + cb]     = v0;
                if (cb + 1 < N) C[(long)rr * ldc + cb + 1] = v1;
            }
        }
    }
}

// ---------------- RoPE (in place on q,k parts of qkv) ----------------
__global__ void rope_k(float* __restrict__ qkv)
{
    int idx = blockIdx.x * 256 + threadIdx.x;
    // layout of idx: t (11b) | part (1b) | head (4b) | d (6b)
    if (idx >= Tt * 2 * NHh * 64) return;
    int d  = idx & 63;
    int hh = (idx >> 6) & 15;
    int p  = (idx >> 10) & 1;
    int t  = idx >> 11;
    float inv = 1.0f / powf(10000.0f, (float)d * (1.0f / 64.0f));
    float ang = (float)t * inv;
    float c = cosf(ang), s = sinf(ang);
    size_t base = (size_t)t * (3 * Hh) + (size_t)p * Hh + hh * HDd;
    float x1v = qkv[base + d];
    float x2v = qkv[base + d + 64];
    qkv[base + d]      = x1v * c - x2v * s;
    qkv[base + d + 64] = x1v * s + x2v * c;
}

// ---------------- fused flash attention (tf32 mma, online softmax) ----------------
// 128 queries x 64 keys per tile; 8 warps, each owns 16 query rows.
// Qs/Ks/Vs stride 132 (frag loads conflict-free), Ps stride 68.
#define FSTR 132
#define PSTR 68
#define FQ   128    // queries per CTA

__global__ __launch_bounds__(256, 1)
void flash_k(const float* __restrict__ qkv, float* __restrict__ ctx)
{
    extern __shared__ float sm[];
    float* Qs = sm;                          // [128][132]
    float* Ks = sm + FQ * FSTR;              // [64][132]
    float* Vs = sm + (FQ + 64) * FSTR;       // [64][132]
    float* Ps = sm + (FQ + 128) * FSTR;      // [128][68]

    int h  = blockIdx.y;
    int qt = gridDim.x - 1 - blockIdx.x;     // longest blocks launch first
    int t0 = qt * FQ;
    int tid = threadIdx.x, warp = tid >> 5, lane = tid & 31;
    int grp = lane >> 2, tid4 = lane & 3;

    // load + convert Q tile (128 x 128)
    for (int i = tid; i < FQ * 32; i += 256) {
        int r = i >> 5, c4 = (i & 31) * 4;
        float4 v = *(const float4*)(qkv + (size_t)(t0 + r) * (3 * Hh) + h * HDd + c4);
        st_tf32x4(&Qs[r * FSTR + c4], v);
    }

    float o[16][4];
    #pragma unroll
    for (int a = 0; a < 16; a++)
        #pragma unroll
        for (int b = 0; b < 4; b++) o[a][b] = 0.f;
    float m0 = -1e30f, m1 = -1e30f, l0 = 0.f, l1 = 0.f;
    int prow = warp * 16 + grp;
    int r0 = t0 + prow;
    int r1 = r0 + 8;
    int wrow_max = t0 + warp * 16 + 15;      // highest query row in this warp

    int ntiles = (t0 + FQ) / 64;
    for (int j = 0; j < ntiles; j++) {
        int s0 = j * 64;
        __syncthreads();
        for (int i = tid; i < 64 * 32; i += 256) {
            int r = i >> 5, c4 = (i & 31) * 4;
            const float* base = qkv + (size_t)(s0 + r) * (3 * Hh) + h * HDd + c4;
            st_tf32x4(&Ks[r * FSTR + c4], *(const float4*)(base + Hh));
            st_tf32x4(&Vs[r * FSTR + c4], *(const float4*)(base + 2 * Hh));
        }
        __syncthreads();

        if (s0 > wrow_max) continue;          // warp-uniform: tile fully masked for this warp

        // ---- scores tile: S = Q Kt ----
        float s[8][4];
        #pragma unroll
        for (int nj = 0; nj < 8; nj++)
            #pragma unroll
            for (int r = 0; r < 4; r++) s[nj][r] = 0.f;
        #pragma unroll
        for (int ks = 0; ks < 16; ks++) {
            unsigned af[4];
            af[0] = __float_as_uint(Qs[prow * FSTR + ks * 8 + tid4]);
            af[1] = __float_as_uint(Qs[(prow + 8) * FSTR + ks * 8 + tid4]);
            af[2] = __float_as_uint(Qs[prow * FSTR + ks * 8 + tid4 + 4]);
            af[3] = __float_as_uint(Qs[(prow + 8) * FSTR + ks * 8 + tid4 + 4]);
            #pragma unroll
            for (int nj = 0; nj < 8; nj++) {
                unsigned b0 = __float_as_uint(Ks[(nj * 8 + grp) * FSTR + ks * 8 + tid4]);
                unsigned b1 = __float_as_uint(Ks[(nj * 8 + grp) * FSTR + ks * 8 + tid4 + 4]);
                mma_tf32(s[nj], af, b0, b1);
            }
        }

        // ---- online softmax ----
        const float scale = 0.08838834764831845f; // 1/sqrt(128)
        bool diag = (s0 + 63 >= t0);               // only last two tiles touch diagonal
        float tm0 = -1e30f, tm1 = -1e30f;
        #pragma unroll
        for (int nj = 0; nj < 8; nj++) {
            #pragma unroll
            for (int r = 0; r < 4; r++) s[nj][r] *= scale;
            if (diag) {
                int c0 = s0 + nj * 8 + tid4 * 2;
                if (c0     > r0) s[nj][0] = -1e30f;
                if (c0 + 1 > r0) s[nj][1] = -1e30f;
                if (c0     > r1) s[nj][2] = -1e30f;
                if (c0 + 1 > r1) s[nj][3] = -1e30f;
            }
            tm0 = fmaxf(tm0, fmaxf(s[nj][0], s[nj][1]));
            tm1 = fmaxf(tm1, fmaxf(s[nj][2], s[nj][3]));
        }
        #pragma unroll
        for (int off = 1; off < 4; off <<= 1) {
            tm0 = fmaxf(tm0, __shfl_xor_sync(0xffffffff, tm0, off));
            tm1 = fmaxf(tm1, __shfl_xor_sync(0xffffffff, tm1, off));
        }
        float nm0 = fmaxf(m0, tm0), nm1 = fmaxf(m1, tm1);
        float f0 = __expf(m0 - nm0), f1 = __expf(m1 - nm1);
        float rs0 = 0.f, rs1 = 0.f;
        #pragma unroll
        for (int nj = 0; nj < 8; nj++) {
            float p0 = __expf(s[nj][0] - nm0);
            float p1 = __expf(s[nj][1] - nm0);
            float p2 = __expf(s[nj][2] - nm1);
            float p3 = __expf(s[nj][3] - nm1);
            rs0 += p0 + p1; rs1 += p2 + p3;
            int pc = nj * 8 + tid4 * 2;
            Ps[prow * PSTR + pc]           = __uint_as_float(f2tf32(p0));
            Ps[prow * PSTR + pc + 1]       = __uint_as_float(f2tf32(p1));
            Ps[(prow + 8) * PSTR + pc]     = __uint_as_float(f2tf32(p2));
            Ps[(prow + 8) * PSTR + pc + 1] = __uint_as_float(f2tf32(p3));
        }
        l0 = l0 * f0 + rs0;
        l1 = l1 * f1 + rs1;
        #pragma unroll
        for (int nj = 0; nj < 16; nj++) {
            o[nj][0] *= f0; o[nj][1] *= f0;
            o[nj][2] *= f1; o[nj][3] *= f1;
        }
        __syncwarp();   // Ps rows are warp-private: warp-level ordering suffices

        // ---- O += P V ----
        #pragma unroll
        for (int ks = 0; ks < 8; ks++) {
            unsigned af[4];
            af[0] = __float_as_uint(Ps[prow * PSTR + ks * 8 + tid4]);
            af[1] = __float_as_uint(Ps[(prow + 8) * PSTR + ks * 8 + tid4]);
            af[2] = __float_as_uint(Ps[prow * PSTR + ks * 8 + tid4 + 4]);
            af[3] = __float_as_uint(Ps[(prow + 8) * PSTR + ks * 8 + tid4 + 4]);
            #pragma unroll
            for (int nj = 0; nj < 16; nj++) {
                unsigned b0 = __float_as_uint(Vs[(ks * 8 + tid4) * FSTR + nj * 8 + grp]);
                unsigned b1 = __float_as_uint(Vs[(ks * 8 + tid4 + 4) * FSTR + nj * 8 + grp]);
                mma_tf32(o[nj], af, b0, b1);
            }
        }
        m0 = nm0; m1 = nm1;
    }

    // reduce l across the quad (each thread held a column subset)
    #pragma unroll
    for (int off = 1; off < 4; off <<= 1) {
        l0 += __shfl_xor_sync(0xffffffff, l0, off);
        l1 += __shfl_xor_sync(0xffffffff, l1, off);
    }
    float inv0 = 1.f / l0, inv1 = 1.f / l1;
    #pragma unroll
    for (int nj = 0; nj < 16; nj++) {
        int cc = h * HDd + nj * 8 + tid4 * 2;
        ctx[(size_t)r0 * Hh + cc]     = o[nj][0] * inv0;
        ctx[(size_t)r0 * Hh + cc + 1] = o[nj][1] * inv0;
        ctx[(size_t)r1 * Hh + cc]     = o[nj][2] * inv1;
        ctx[(size_t)r1 * Hh + cc + 1] = o[nj][3] * inv1;
    }
}

// ---------------- router top-2 ----------------
__global__ void topk_k(const float* __restrict__ lg, float* __restrict__ topw,
                       int* __restrict__ topi, int* __restrict__ cnt)
{
    int t = blockIdx.x * blockDim.x + threadIdx.x;
    if (t >= Tt) return;
    const float* l = lg + (size_t)t * Ee;
    float b0 = -1e30f; int i0 = 0;
    #pragma unroll
    for (int e = 0; e < Ee; e++) { float v = l[e]; if (v > b0) { b0 = v; i0 = e; } }
    float b1 = -1e30f; int i1 = 0;
    #pragma unroll
    for (int e = 0; e < Ee; e++) { if (e == i0) continue; float v = l[e]; if (v > b1) { b1 = v; i1 = e; } }
    float e1 = expf(b1 - b0);
    float s = 1.0f + e1;
    topw[t * 2]     = 1.0f / s;
    topw[t * 2 + 1] = e1 / s;
    topi[t * 2]     = i0;
    topi[t * 2 + 1] = i1;
    atomicAdd(&cnt[i0], 1);
    atomicAdd(&cnt[i1], 1);
}

// ---------------- scan: padded offsets (pad to 128 = GBM) ----------------
__global__ void scan_k(const int* __restrict__ cnt, int* __restrict__ poff,
                       int* __restrict__ pcnt, int* __restrict__ fill)
{
    if (threadIdx.x == 0 && blockIdx.x == 0) {
        int run = 0;
        for (int e = 0; e < Ee; e++) {
            poff[e] = run;
            int pc = (cnt[e] + 127) & ~127;
            pcnt[e] = pc;
            run += pc;
            fill[e] = 0;
        }
    }
}

// ---------------- scatter: gather h2 rows into expert-sorted X ----------------
__global__ void scatter_k(const float* __restrict__ h2, const int* __restrict__ topi,
                          const int* __restrict__ poff, int* __restrict__ fill,
                          int* __restrict__ pos, float* __restrict__ X)
{
    int a = blockIdx.x;   // assignment id 0..2T-1
    __shared__ int sp;
    if (threadIdx.x == 0) {
        int e = topi[a];
        sp = poff[e] + atomicAdd(&fill[e], 1);
        pos[a] = sp;
    }
    __syncthreads();
    int p = sp;
    int t = a >> 1;
    const float* src = h2 + (size_t)t * Hh;
    float* dst = X + (size_t)p * Hh;
    for (int i = threadIdx.x; i < Hh; i += 256) dst[i] = src[i];
}

// ---------------- silu(g)*u ----------------
__global__ void silu_mul_k(const float* __restrict__ in, float* __restrict__ out,
                           long total, int Fh, int ldin)
{
    long idx = (long)blockIdx.x * 256 + threadIdx.x;
    if (idx >= total) return;
    long r = idx / Fh;
    int  f = (int)(idx - r * Fh);
    float gv = in[r * ldin + f];
    float uv = in[r * ldin + Fh + f];
    float sv = gv / (1.0f + expf(-gv));
    out[idx] = sv * uv;
}

// ---------------- final combine ----------------
__global__ void final_k(const float* __restrict__ x1, const float* __restrict__ sh,
                        const float* __restrict__ D, const float* __restrict__ topw,
                        const int* __restrict__ pos, float* __restrict__ out)
{
    int idx = blockIdx.x * 256 + threadIdx.x;
    int t = idx >> 11;       // /2048
    int c = idx & 2047;
    if (t >= Tt) return;
    int a = t * 2;
    float v = x1[idx] + sh[idx];
    v += topw[a]     * D[(size_t)pos[a]     * Hh + c];
    v += topw[a + 1] * D[(size_t)pos[a + 1] * Hh + c];
    out[idx] = v;
}

// ---------------- host side ----------------
template <typename Tp>
static Tp* symaddr(const void* sym)
{
    void* p = nullptr;
    cudaGetSymbolAddress(&p, sym);
    return (Tp*)p;
}

static void launch_gemm(const float* A, int lda, const float* B, int ldb,
                        float* C, int ldc, int M, int N, int K,
                        const float* Cadd, long sAz, long sBz, long sCz, int Z,
                        const int* goff, const int* gcnt)
{
    static int smem_set = 0;
    if (!smem_set) {
        cudaFuncSetAttribute(gemm_tc, cudaFuncAttributeMaxDynamicSharedMemorySize,
                             GSMEM_BYTES);
        smem_set = 1;
    }
    dim3 grid((N + GBN - 1) / GBN, (M + GBM - 1) / GBM, Z);
    gemm_tc<<<grid, 256, GSMEM_BYTES>>>(A, lda, B, ldb, C, ldc, M, N, K, Cadd,
                                        sAz, sBz, sCz, goff, gcnt);
}

extern "C" void kernel_launch(void* const* d_in, const int* in_sizes, int n_in,
                              void* d_out, int out_size)
{
    const float* x        = (const float*)d_in[0];
    const float* gamma1   = (const float*)d_in[1];
    const float* gamma2   = (const float*)d_in[2];
    const float* w_qkv    = (const float*)d_in[3];
    const float* w_o      = (const float*)d_in[4];
    const float* gate_w   = (const float*)d_in[5];
    const float* moe_up   = (const float*)d_in[6];
    const float* moe_down = (const float*)d_in[7];
    const float* sw13     = (const float*)d_in[8];
    const float* sdown    = (const float*)d_in[9];
    float* out = (float*)d_out;

    float* h    = symaddr<float>(&g_h);
    float* qkv  = symaddr<float>(&g_qkv);
    float* ctx  = symaddr<float>(&g_ctx);
    float* x1   = symaddr<float>(&g_x1);
    float* h2   = symaddr<float>(&g_h2);
    float* lg   = symaddr<float>(&g_lg);
    float* topw = symaddr<float>(&g_topw);
    int*   topi = symaddr<int>(&g_topi);
    int*   cnt  = symaddr<int>(&g_cnt);
    int*   poff = symaddr<int>(&g_poff);
    int*   pcnt = symaddr<int>(&g_pcnt);
    int*   fill = symaddr<int>(&g_fill);
    int*   pos  = symaddr<int>(&g_pos);
    float* X    = symaddr<float>(&g_X);
    float* gu   = symaddr<float>(&g_gu);
    float* act  = symaddr<float>(&g_act);
    float* D    = symaddr<float>(&g_D);
    float* sg   = symaddr<float>(&g_sg);
    float* sact = symaddr<float>(&g_sact);
    float* sh   = symaddr<float>(&g_sh);

    // 1. h = rmsnorm(x, gamma1)
    rmsnorm_k<<<Tt, 256>>>(x, gamma1, h);
    // 2. qkv = h @ w_qkv
    launch_gemm(h, Hh, w_qkv, 3 * Hh, qkv, 3 * Hh, Tt, 3 * Hh, Hh,
                nullptr, 0, 0, 0, 1, nullptr, nullptr);
    // 3. rope(q, k)
    rope_k<<<(Tt * 2 * NHh * 64 + 255) / 256, 256>>>(qkv);
    // 4-6. fused flash attention -> ctx
    {
        int smem = ((FQ + 128) * FSTR + FQ * PSTR) * (int)sizeof(float);
        cudaFuncSetAttribute(flash_k, cudaFuncAttributeMaxDynamicSharedMemorySize, smem);
        dim3 grid(Tt / FQ, NHh);
        flash_k<<<grid, 256, smem>>>(qkv, ctx);
    }
    // 7. x1 = x + ctx @ w_o
    launch_gemm(ctx, Hh, w_o, Hh, x1, Hh, Tt, Hh, Hh,
                x, 0, 0, 0, 1, nullptr, nullptr);
    // 8. h2 = rmsnorm(x1, gamma2)
    rmsnorm_k<<<Tt, 256>>>(x1, gamma2, h2);
    // 9. router logits
    launch_gemm(h2, Hh, gate_w, Ee, lg, Ee, Tt, Ee, Hh,
                nullptr, 0, 0, 0, 1, nullptr, nullptr);
    // 10. top-2 (+ counts)
    cudaMemsetAsync(cnt, 0, Ee * sizeof(int));
    topk_k<<<(Tt + 255) / 256, 256>>>(lg, topw, topi, cnt);
    // 11. scan -> padded offsets
    scan_k<<<1, 32>>>(cnt, poff, pcnt, fill);
    // 12. gather rows by expert
    scatter_k<<<Tt * 2, 256>>>(h2, topi, poff, fill, pos, X);
    // 13. grouped up-proj: gu = X @ moe_up[e]
    launch_gemm(X, Hh, moe_up, 2 * Ff, gu, 2 * Ff, Tt, 2 * Ff, Hh,
                nullptr, 0, (long)Hh * 2 * Ff, 0, Ee, poff, pcnt);
    // 14. act = silu(g)*u over all CAP rows (padded rows unread later)
    {
        long total = (long)CAP * Ff;
        silu_mul_k<<<(int)((total + 255) / 256), 256>>>(gu, act, total, Ff, 2 * Ff);
    }
    // 15. grouped down-proj: D = act @ moe_down[e]
    launch_gemm(act, Ff, moe_down, Hh, D, Hh, Tt, Hh, Ff,
                nullptr, 0, (long)Ff * Hh, 0, Ee, poff, pcnt);
    // 16. shared FFN
    launch_gemm(h2, Hh, sw13, 2 * SF, sg, 2 * SF, Tt, 2 * SF, Hh,
                nullptr, 0, 0, 0, 1, nullptr, nullptr);
    {
        long total = (long)Tt * SF;
        silu_mul_k<<<(int)((total + 255) / 256), 256>>>(sg, sact, total, SF, 2 * SF);
    }
    launch_gemm(sact, SF, sdown, Hh, sh, Hh, Tt, Hh, SF,
                nullptr, 0, 0, 0, 1, nullptr, nullptr);
    // 17. out = x1 + moe + shared
    final_k<<<(Tt * Hh) / 256, 256>>>(x1, sh, D, topw, pos, out);
}